// round 12
// baseline (speedup 1.0000x reference)
#include <cuda_runtime.h>

// CentDif: 6th-order central difference + 2-channel advection combine.
// u: [16384, 2, 2048] fp32. FINAL (converged at HBM mixed-R/W ceiling):
// no smem, no barriers; each thread computes 8 consecutive outputs from a
// 16-float register window per channel (4x LDG.128), L1 absorbs inter-thread
// halo overlap. 128-thread CTAs (half-row each); streaming stores.

#define M_DIM 16384
#define L_DIM 2048
#define IGST  10
#define NTHREADS 128   // half-row: 128 * 8 = 1024 floats

__global__ __launch_bounds__(NTHREADS) void centdif_kernel(
    const float* __restrict__ u, float* __restrict__ out)
{
    const int bid  = blockIdx.x;
    const int m    = bid >> 1;
    const int half = bid & 1;
    const size_t base = (size_t)m * (2 * L_DIM);
    const int l0 = (half * (L_DIM / 2)) + threadIdx.x * 8;

    float4* o0 = (float4*)(out + base + l0);
    float4* o1 = (float4*)(out + base + L_DIM + l0);

    // Fully-ghost spans: outputs exactly 0; also avoids OOB window loads.
    if (l0 + 7 < IGST || l0 >= L_DIM - IGST) {
        const float4 z = make_float4(0.f, 0.f, 0.f, 0.f);
        __stcs(o0 + 0, z); __stcs(o0 + 1, z);
        __stcs(o1 + 0, z); __stcs(o1 + 1, z);
        return;
    }

    const float c = (float)(1.0 / (60.0 * 0.012));  // 1/(60*DX)

    // Register window: a[k] = u0[l0-4+k], b[k] = u1[l0-4+k], k=0..15.
    // l0-4 is a multiple of 4 -> aligned float4 loads; front-batched for MLP.
    const float4* p0 = (const float4*)(u + base + l0 - 4);
    const float4* p1 = (const float4*)(u + base + L_DIM + l0 - 4);

    float4 va[4], vb[4];
    #pragma unroll
    for (int q = 0; q < 4; ++q) va[q] = __ldg(p0 + q);
    #pragma unroll
    for (int q = 0; q < 4; ++q) vb[q] = __ldg(p1 + q);

    float a[16], b[16];
    #pragma unroll
    for (int q = 0; q < 4; ++q) {
        a[4*q+0] = va[q].x; a[4*q+1] = va[q].y; a[4*q+2] = va[q].z; a[4*q+3] = va[q].w;
        b[4*q+0] = vb[q].x; b[4*q+1] = vb[q].y; b[4*q+2] = vb[q].z; b[4*q+3] = vb[q].w;
    }

    float r0[8], r1[8];
    #pragma unroll
    for (int i = 0; i < 8; ++i) {
        const int l = l0 + i;
        float du0 = 0.0f, du1 = 0.0f;
        if (l >= IGST && l < L_DIM - IGST) {
            // taps: l-3 -> a[i+1], l-2 -> a[i+2], l-1 -> a[i+3],
            //       l+1 -> a[i+5], l+2 -> a[i+6], l+3 -> a[i+7]
            du0 = (-a[i+1] + 9.0f*a[i+2] - 45.0f*a[i+3]
                   + 45.0f*a[i+5] - 9.0f*a[i+6] + a[i+7]) * c;
            du1 = (-b[i+1] + 9.0f*b[i+2] - 45.0f*b[i+3]
                   + 45.0f*b[i+5] - 9.0f*b[i+6] + b[i+7]) * c;
        }
        const float uu0 = a[i+4];   // u0[l]
        const float uu1 = b[i+4];   // u1[l]
        r0[i] = -(uu1 * du0 + uu0 * du1);
        r1[i] = -(2.0f * du0 + uu1 * du1);
    }

    __stcs(o0 + 0, make_float4(r0[0], r0[1], r0[2], r0[3]));
    __stcs(o0 + 1, make_float4(r0[4], r0[5], r0[6], r0[7]));
    __stcs(o1 + 0, make_float4(r1[0], r1[1], r1[2], r1[3]));
    __stcs(o1 + 1, make_float4(r1[4], r1[5], r1[6], r1[7]));
}

extern "C" void kernel_launch(void* const* d_in, const int* in_sizes, int n_in,
                              void* d_out, int out_size)
{
    const float* u = (const float*)d_in[0];
    float* out = (float*)d_out;
    centdif_kernel<<<M_DIM * 2, NTHREADS>>>(u, out);
}

// round 13
// speedup vs baseline: 1.0023x; 1.0023x over previous
#include <cuda_runtime.h>

// CentDif: 6th-order central difference + 2-channel advection combine.
// u: [16384, 2, 2048] fp32. Converged streaming kernel:
//  - no smem, no barriers; thread t computes outputs [8t+4, 8t+12)
//  - window [8t, 8t+16) per channel: 2x 256-bit ld.global.nc, 32B-aligned,
//    L2::evict_first (reads are single-use at L2 scope)
//  - evict-first streaming stores (__stcs)
//  - lane 255 zero-fills the 4-float ghost ends of each channel row.

#define M_DIM 16384
#define L_DIM 2048
#define IGST  10
#define NTHREADS 256

__device__ __forceinline__ void ldg256_ef(const float* __restrict__ p, float* r) {
    asm volatile(
        "ld.global.nc.L2::evict_first.v8.f32 {%0,%1,%2,%3,%4,%5,%6,%7}, [%8];"
        : "=f"(r[0]), "=f"(r[1]), "=f"(r[2]), "=f"(r[3]),
          "=f"(r[4]), "=f"(r[5]), "=f"(r[6]), "=f"(r[7])
        : "l"(p));
}

__global__ __launch_bounds__(NTHREADS) void centdif_kernel(
    const float* __restrict__ u, float* __restrict__ out)
{
    const int m = blockIdx.x;
    const size_t base = (size_t)m * (2 * L_DIM);
    const int t = threadIdx.x;

    if (t == NTHREADS - 1) {
        // Ghost ends: l in [0,4) and [2044,2048), both channels -> exactly 0.
        const float4 z = make_float4(0.f, 0.f, 0.f, 0.f);
        __stcs((float4*)(out + base), z);
        __stcs((float4*)(out + base + L_DIM - 4), z);
        __stcs((float4*)(out + base + L_DIM), z);
        __stcs((float4*)(out + base + 2 * L_DIM - 4), z);
        return;
    }

    const float c = (float)(1.0 / (60.0 * 0.012));  // 1/(60*DX)

    // Window: a[k] = u0[8t + k], b[k] = u1[8t + k], k = 0..15
    // (byte offset 32t -> 32B-aligned 256-bit loads; front-batched for MLP).
    float a[16], b[16];
    const float* w0 = u + base + 8 * t;
    const float* w1 = u + base + L_DIM + 8 * t;
    ldg256_ef(w0,     a);
    ldg256_ef(w0 + 8, a + 8);
    ldg256_ef(w1,     b);
    ldg256_ef(w1 + 8, b + 8);

    // Outputs l = 8t + 4 + i, i = 0..7.
    // Taps: l-3 -> a[i+1], l-2 -> a[i+2], l-1 -> a[i+3],
    //       l+1 -> a[i+5], l+2 -> a[i+6], l+3 -> a[i+7]; u[l] -> a[i+4].
    const int l0 = 8 * t + 4;
    float r0[8], r1[8];
    #pragma unroll
    for (int i = 0; i < 8; ++i) {
        const int l = l0 + i;
        float du0 = 0.0f, du1 = 0.0f;
        if (l >= IGST && l < L_DIM - IGST) {
            du0 = (-a[i+1] + 9.0f*a[i+2] - 45.0f*a[i+3]
                   + 45.0f*a[i+5] - 9.0f*a[i+6] + a[i+7]) * c;
            du1 = (-b[i+1] + 9.0f*b[i+2] - 45.0f*b[i+3]
                   + 45.0f*b[i+5] - 9.0f*b[i+6] + b[i+7]) * c;
        }
        const float uu0 = a[i+4];
        const float uu1 = b[i+4];
        r0[i] = -(uu1 * du0 + uu0 * du1);
        r1[i] = -(2.0f * du0 + uu1 * du1);
    }

    float4* o0 = (float4*)(out + base + l0);
    float4* o1 = (float4*)(out + base + L_DIM + l0);
    __stcs(o0 + 0, make_float4(r0[0], r0[1], r0[2], r0[3]));
    __stcs(o0 + 1, make_float4(r0[4], r0[5], r0[6], r0[7]));
    __stcs(o1 + 0, make_float4(r1[0], r1[1], r1[2], r1[3]));
    __stcs(o1 + 1, make_float4(r1[4], r1[5], r1[6], r1[7]));
}

extern "C" void kernel_launch(void* const* d_in, const int* in_sizes, int n_in,
                              void* d_out, int out_size)
{
    const float* u = (const float*)d_in[0];
    float* out = (float*)d_out;
    centdif_kernel<<<M_DIM, NTHREADS>>>(u, out);
}

// round 14
// speedup vs baseline: 1.0058x; 1.0035x over previous
#include <cuda_runtime.h>

// CentDif: 6th-order central difference + 2-channel advection combine.
// u: [16384, 2, 2048] fp32. FINAL converged kernel (HBM mixed-R/W ceiling):
//  - no smem, no barriers; thread t computes outputs [8t+4, 8t+12)
//  - window [8t, 8t+16) per channel: 2x 256-bit ld.global.nc, 32B-aligned,
//    L2::evict_first (reads are single-use at L2 scope)
//  - evict-first streaming stores (__stcs)
//  - lane 255 zero-fills the 4-float ghost ends of each channel row.

#define M_DIM 16384
#define L_DIM 2048
#define IGST  10
#define NTHREADS 256

__device__ __forceinline__ void ldg256_ef(const float* __restrict__ p, float* r) {
    asm volatile(
        "ld.global.nc.L2::evict_first.v8.f32 {%0,%1,%2,%3,%4,%5,%6,%7}, [%8];"
        : "=f"(r[0]), "=f"(r[1]), "=f"(r[2]), "=f"(r[3]),
          "=f"(r[4]), "=f"(r[5]), "=f"(r[6]), "=f"(r[7])
        : "l"(p));
}

__global__ __launch_bounds__(NTHREADS) void centdif_kernel(
    const float* __restrict__ u, float* __restrict__ out)
{
    const int m = blockIdx.x;
    const size_t base = (size_t)m * (2 * L_DIM);
    const int t = threadIdx.x;

    if (t == NTHREADS - 1) {
        // Ghost ends: l in [0,4) and [2044,2048), both channels -> exactly 0.
        const float4 z = make_float4(0.f, 0.f, 0.f, 0.f);
        __stcs((float4*)(out + base), z);
        __stcs((float4*)(out + base + L_DIM - 4), z);
        __stcs((float4*)(out + base + L_DIM), z);
        __stcs((float4*)(out + base + 2 * L_DIM - 4), z);
        return;
    }

    const float c = (float)(1.0 / (60.0 * 0.012));  // 1/(60*DX)

    // Window: a[k] = u0[8t + k], b[k] = u1[8t + k], k = 0..15
    // (byte offset 32t -> 32B-aligned 256-bit loads; front-batched for MLP).
    float a[16], b[16];
    const float* w0 = u + base + 8 * t;
    const float* w1 = u + base + L_DIM + 8 * t;
    ldg256_ef(w0,     a);
    ldg256_ef(w0 + 8, a + 8);
    ldg256_ef(w1,     b);
    ldg256_ef(w1 + 8, b + 8);

    // Outputs l = 8t + 4 + i, i = 0..7.
    // Taps: l-3 -> a[i+1], l-2 -> a[i+2], l-1 -> a[i+3],
    //       l+1 -> a[i+5], l+2 -> a[i+6], l+3 -> a[i+7]; u[l] -> a[i+4].
    const int l0 = 8 * t + 4;
    float r0[8], r1[8];
    #pragma unroll
    for (int i = 0; i < 8; ++i) {
        const int l = l0 + i;
        float du0 = 0.0f, du1 = 0.0f;
        if (l >= IGST && l < L_DIM - IGST) {
            du0 = (-a[i+1] + 9.0f*a[i+2] - 45.0f*a[i+3]
                   + 45.0f*a[i+5] - 9.0f*a[i+6] + a[i+7]) * c;
            du1 = (-b[i+1] + 9.0f*b[i+2] - 45.0f*b[i+3]
                   + 45.0f*b[i+5] - 9.0f*b[i+6] + b[i+7]) * c;
        }
        const float uu0 = a[i+4];
        const float uu1 = b[i+4];
        r0[i] = -(uu1 * du0 + uu0 * du1);
        r1[i] = -(2.0f * du0 + uu1 * du1);
    }

    float4* o0 = (float4*)(out + base + l0);
    float4* o1 = (float4*)(out + base + L_DIM + l0);
    __stcs(o0 + 0, make_float4(r0[0], r0[1], r0[2], r0[3]));
    __stcs(o0 + 1, make_float4(r0[4], r0[5], r0[6], r0[7]));
    __stcs(o1 + 0, make_float4(r1[0], r1[1], r1[2], r1[3]));
    __stcs(o1 + 1, make_float4(r1[4], r1[5], r1[6], r1[7]));
}

extern "C" void kernel_launch(void* const* d_in, const int* in_sizes, int n_in,
                              void* d_out, int out_size)
{
    const float* u = (const float*)d_in[0];
    float* out = (float*)d_out;
    centdif_kernel<<<M_DIM, NTHREADS>>>(u, out);
}

// round 15
// speedup vs baseline: 1.0078x; 1.0020x over previous
#include <cuda_runtime.h>

// CentDif: 6th-order central difference + 2-channel advection combine.
// u: [16384, 2, 2048] fp32. Converged streaming kernel, 512-thread CTAs
// covering two m-rows each (threads 0-255 -> row 2*bid, 256-511 -> 2*bid+1).
// Per-thread shape identical to the best-profiled variant:
//  - no smem, no barriers; thread computes outputs [8t+4, 8t+12) of its row
//  - window [8t, 8t+16) per channel: 2x 256-bit ld.global.nc, 32B-aligned,
//    L2::evict_first; evict-first streaming stores
//  - lane 255 of each half zero-fills the 4-float ghost ends of its row.

#define M_DIM 16384
#define L_DIM 2048
#define IGST  10
#define NTHREADS 512
#define TPR   256          // threads per row

__device__ __forceinline__ void ldg256_ef(const float* __restrict__ p, float* r) {
    asm volatile(
        "ld.global.nc.L2::evict_first.v8.f32 {%0,%1,%2,%3,%4,%5,%6,%7}, [%8];"
        : "=f"(r[0]), "=f"(r[1]), "=f"(r[2]), "=f"(r[3]),
          "=f"(r[4]), "=f"(r[5]), "=f"(r[6]), "=f"(r[7])
        : "l"(p));
}

__global__ __launch_bounds__(NTHREADS) void centdif_kernel(
    const float* __restrict__ u, float* __restrict__ out)
{
    const int m = blockIdx.x * 2 + (threadIdx.x / TPR);
    const int t = threadIdx.x % TPR;
    const size_t base = (size_t)m * (2 * L_DIM);

    if (t == TPR - 1) {
        // Ghost ends: l in [0,4) and [2044,2048), both channels -> exactly 0.
        const float4 z = make_float4(0.f, 0.f, 0.f, 0.f);
        __stcs((float4*)(out + base), z);
        __stcs((float4*)(out + base + L_DIM - 4), z);
        __stcs((float4*)(out + base + L_DIM), z);
        __stcs((float4*)(out + base + 2 * L_DIM - 4), z);
        return;
    }

    const float c = (float)(1.0 / (60.0 * 0.012));  // 1/(60*DX)

    // Window: a[k] = u0[8t + k], b[k] = u1[8t + k], k = 0..15
    // (byte offset 32t -> 32B-aligned 256-bit loads; front-batched for MLP).
    float a[16], b[16];
    const float* w0 = u + base + 8 * t;
    const float* w1 = u + base + L_DIM + 8 * t;
    ldg256_ef(w0,     a);
    ldg256_ef(w0 + 8, a + 8);
    ldg256_ef(w1,     b);
    ldg256_ef(w1 + 8, b + 8);

    // Outputs l = 8t + 4 + i, i = 0..7.
    // Taps: l-3 -> a[i+1], l-2 -> a[i+2], l-1 -> a[i+3],
    //       l+1 -> a[i+5], l+2 -> a[i+6], l+3 -> a[i+7]; u[l] -> a[i+4].
    const int l0 = 8 * t + 4;
    float r0[8], r1[8];
    #pragma unroll
    for (int i = 0; i < 8; ++i) {
        const int l = l0 + i;
        float du0 = 0.0f, du1 = 0.0f;
        if (l >= IGST && l < L_DIM - IGST) {
            du0 = (-a[i+1] + 9.0f*a[i+2] - 45.0f*a[i+3]
                   + 45.0f*a[i+5] - 9.0f*a[i+6] + a[i+7]) * c;
            du1 = (-b[i+1] + 9.0f*b[i+2] - 45.0f*b[i+3]
                   + 45.0f*b[i+5] - 9.0f*b[i+6] + b[i+7]) * c;
        }
        const float uu0 = a[i+4];
        const float uu1 = b[i+4];
        r0[i] = -(uu1 * du0 + uu0 * du1);
        r1[i] = -(2.0f * du0 + uu1 * du1);
    }

    float4* o0 = (float4*)(out + base + l0);
    float4* o1 = (float4*)(out + base + L_DIM + l0);
    __stcs(o0 + 0, make_float4(r0[0], r0[1], r0[2], r0[3]));
    __stcs(o0 + 1, make_float4(r0[4], r0[5], r0[6], r0[7]));
    __stcs(o1 + 0, make_float4(r1[0], r1[1], r1[2], r1[3]));
    __stcs(o1 + 1, make_float4(r1[4], r1[5], r1[6], r1[7]));
}

extern "C" void kernel_launch(void* const* d_in, const int* in_sizes, int n_in,
                              void* d_out, int out_size)
{
    const float* u = (const float*)d_in[0];
    float* out = (float*)d_out;
    centdif_kernel<<<M_DIM / 2, NTHREADS>>>(u, out);
}